// round 6
// baseline (speedup 1.0000x reference)
#include <cuda_runtime.h>
#include <cstddef>

#define C_DIM 64
#define K_DIM 64
#define P_DIM (256 * 256)        // H*W = 65536
#define RED_BLOCKS 256           // reduction blocks (256 pixels each)
#define N4_PER_REP (C_DIM * P_DIM / 4)   // 1,048,576 float4 per replica
#define CHUNKS_PER_REP 1024
#define F4_PER_CHUNK (N4_PER_REP / CHUNKS_PER_REP)  // 1024 float4 = 16KB

// Transposed partials: g_partial[i][r] -> means reads contiguous r (coalesced).
// Written unconditionally each launch, no zeroing needed.
__device__ float g_partial[K_DIM * C_DIM][RED_BLOCKS];   // 4 MB
__device__ float g_pcnt[K_DIM][RED_BLOCKS];              // 64 KB
__device__ unsigned int g_ticket;                        // zero-init; reset by last block

// ---------------------------------------------------------------------------
// Single fused kernel (R4 structure + last-block means):
//   blocks [0, 256)       : per-region partial sums; last finisher also
//                           computes the means (ticket pattern, no polling)
//   blocks [256, 256+64K) : 1 GiB broadcast copy (DRAM-write-bound, ~81% spec)
// ---------------------------------------------------------------------------
__global__ __launch_bounds__(256) void fused_kernel(
    const float* __restrict__ x, const float* __restrict__ oh,
    float4* __restrict__ out4, float* __restrict__ out_means)
{
    int bid = blockIdx.x;
    int tid = threadIdx.x;

    if (bid < RED_BLOCKS) {
        // ---- reduction path: 256 pixels per block ----
        __shared__ float ssum[K_DIM][C_DIM + 1];  // padded rows vs bank conflicts
        __shared__ float scnt[K_DIM];
        __shared__ unsigned int s_last;

        for (int i = tid; i < K_DIM * (C_DIM + 1); i += 256)
            (&ssum[0][0])[i] = 0.0f;
        if (tid < K_DIM) scnt[tid] = 0.0f;
        __syncthreads();

        int p = bid * 256 + tid;

        // Recover the one-hot label (coalesced scan over K).
        int label = 0;
        #pragma unroll 8
        for (int k = 0; k < K_DIM; k++) {
            if (__ldg(&oh[(size_t)k * P_DIM + p]) != 0.0f) label = k;
        }
        atomicAdd(&scnt[label], 1.0f);

        #pragma unroll 8
        for (int c = 0; c < C_DIM; c++) {
            atomicAdd(&ssum[label][c], __ldg(&x[(size_t)c * P_DIM + p]));
        }
        __syncthreads();

        // Flush to transposed partial slot.
        for (int i = tid; i < K_DIM * C_DIM; i += 256) {
            g_partial[i][bid] = ssum[i >> 6][i & 63];
        }
        if (tid < K_DIM) g_pcnt[tid][bid] = scnt[tid];

        // Ticket: last block to finish computes the means (all partials are
        // globally visible to it thanks to fence + atomic acquire chain).
        __syncthreads();
        __threadfence();
        if (tid == 0)
            s_last = (atomicAdd(&g_ticket, 1u) == RED_BLOCKS - 1) ? 1u : 0u;
        __syncthreads();

        if (s_last) {
            __threadfence();  // acquire pairing

            // 8 warps x 512 outputs each; warp-per-output over contiguous r.
            int warp = tid >> 5;
            int lane = tid & 31;
            for (int wg = warp; wg < K_DIM * C_DIM; wg += 8) {
                const float4* prow = (const float4*)&g_partial[wg][0];   // 64 f4
                const float4* crow = (const float4*)&g_pcnt[wg >> 6][0]; // 64 f4

                float4 a  = __ldg(prow + lane);
                float4 b  = __ldg(prow + 32 + lane);
                float4 ca = __ldg(crow + lane);
                float4 cb = __ldg(crow + 32 + lane);

                float s   = (a.x + a.y) + (a.z + a.w) + (b.x + b.y) + (b.z + b.w);
                float cnt = (ca.x + ca.y) + (ca.z + ca.w) + (cb.x + cb.y) + (cb.z + cb.w);

                #pragma unroll
                for (int off = 16; off > 0; off >>= 1) {
                    s   += __shfl_xor_sync(0xFFFFFFFFu, s, off);
                    cnt += __shfl_xor_sync(0xFFFFFFFFu, cnt, off);
                }

                if (lane == 0) {
                    float denom = cnt + (cnt == 0.0f ? 1.0f : 0.0f);
                    out_means[wg] = s / denom;
                }
            }

            // Reset ticket for the next graph replay (all 256 increments for
            // this launch have already been observed).
            __syncthreads();
            if (tid == 0) atomicExch(&g_ticket, 0u);
        }
    } else {
        // ---- broadcast path: one 16 KB chunk of one replica ----
        int b  = bid - RED_BLOCKS;
        int k  = b >> 10;                    // replica index
        int cb = b & (CHUNKS_PER_REP - 1);

        const float4* src = (const float4*)x + (size_t)cb * F4_PER_CHUNK;
        float4* dst = out4 + (size_t)k * N4_PER_REP + (size_t)cb * F4_PER_CHUNK;

        float4 v0 = __ldg(src + tid);
        float4 v1 = __ldg(src + 256 + tid);
        float4 v2 = __ldg(src + 512 + tid);
        float4 v3 = __ldg(src + 768 + tid);
        __stcs(dst + tid,       v0);
        __stcs(dst + 256 + tid, v1);
        __stcs(dst + 512 + tid, v2);
        __stcs(dst + 768 + tid, v3);
    }
}

// ---------------------------------------------------------------------------
extern "C" void kernel_launch(void* const* d_in, const int* in_sizes, int n_in,
                              void* d_out, int out_size)
{
    const float* x  = (const float*)d_in[0];   // [1, 64, 256, 256]
    const float* oh = (const float*)d_in[1];   // [1, 64, 256, 256] one-hot
    float* out = (float*)d_out;

    // Output layout: input_r (K*C*H*W floats) then regional_means (K*C).
    float* out_means = out + (size_t)out_size - (size_t)(K_DIM * C_DIM);

    fused_kernel<<<RED_BLOCKS + K_DIM * CHUNKS_PER_REP, 256>>>(
        x, oh, (float4*)out, out_means);
}

// round 7
// speedup vs baseline: 2.3044x; 2.3044x over previous
#include <cuda_runtime.h>
#include <cstddef>

#define C_DIM 64
#define K_DIM 64
#define P_DIM (256 * 256)        // H*W = 65536
#define RED_BLOCKS 256           // reduction blocks (256 pixels each)
#define MEANS_BLOCKS 512         // means blocks in kernel 2 (warp per output)
#define N4_PER_REP (C_DIM * P_DIM / 4)   // 1,048,576 float4 per replica
#define CHUNKS_PER_REP 1024
#define TOTAL_CHUNKS (K_DIM * CHUNKS_PER_REP)       // 65536
#define HALF_CHUNKS (TOTAL_CHUNKS / 2)              // 32768
#define F4_PER_CHUNK (N4_PER_REP / CHUNKS_PER_REP)  // 1024 float4 = 16KB

// Transposed partials: g_partial[i][r] -> means reads contiguous r (coalesced).
// Written unconditionally each launch, no zeroing needed.
__device__ float g_partial[K_DIM * C_DIM][RED_BLOCKS];   // 4 MB
__device__ float g_pcnt[K_DIM][RED_BLOCKS];              // 64 KB

// ---------------------------------------------------------------------------
// Shared broadcast chunk copier: chunk g in [0, TOTAL_CHUNKS).
// ---------------------------------------------------------------------------
__device__ __forceinline__ void copy_chunk(
    const float* __restrict__ x, float4* __restrict__ out4, int g, int tid)
{
    int k  = g >> 10;                    // replica index
    int cb = g & (CHUNKS_PER_REP - 1);

    const float4* src = (const float4*)x + (size_t)cb * F4_PER_CHUNK;
    float4* dst = out4 + (size_t)k * N4_PER_REP + (size_t)cb * F4_PER_CHUNK;

    float4 v0 = __ldg(src + tid);
    float4 v1 = __ldg(src + 256 + tid);
    float4 v2 = __ldg(src + 512 + tid);
    float4 v3 = __ldg(src + 768 + tid);
    __stcs(dst + tid,       v0);
    __stcs(dst + 256 + tid, v1);
    __stcs(dst + 512 + tid, v2);
    __stcs(dst + 768 + tid, v3);
}

// ---------------------------------------------------------------------------
// Kernel 1: reduction blocks + first half of the broadcast (R4 pattern).
// ---------------------------------------------------------------------------
__global__ __launch_bounds__(256) void fused_a_kernel(
    const float* __restrict__ x, const float* __restrict__ oh,
    float4* __restrict__ out4)
{
    int bid = blockIdx.x;
    int tid = threadIdx.x;

    if (bid < RED_BLOCKS) {
        // ---- reduction path: 256 pixels per block ----
        __shared__ float ssum[K_DIM][C_DIM + 1];  // padded rows vs bank conflicts
        __shared__ float scnt[K_DIM];

        for (int i = tid; i < K_DIM * (C_DIM + 1); i += 256)
            (&ssum[0][0])[i] = 0.0f;
        if (tid < K_DIM) scnt[tid] = 0.0f;
        __syncthreads();

        int p = bid * 256 + tid;

        // Recover the one-hot label (coalesced scan over K).
        int label = 0;
        #pragma unroll 8
        for (int k = 0; k < K_DIM; k++) {
            if (__ldg(&oh[(size_t)k * P_DIM + p]) != 0.0f) label = k;
        }
        atomicAdd(&scnt[label], 1.0f);

        #pragma unroll 8
        for (int c = 0; c < C_DIM; c++) {
            atomicAdd(&ssum[label][c], __ldg(&x[(size_t)c * P_DIM + p]));
        }
        __syncthreads();

        // Flush to transposed partial slot (plain stores).
        for (int i = tid; i < K_DIM * C_DIM; i += 256) {
            g_partial[i][bid] = ssum[i >> 6][i & 63];
        }
        if (tid < K_DIM) g_pcnt[tid][bid] = scnt[tid];
    } else {
        copy_chunk(x, out4, bid - RED_BLOCKS, tid);   // chunks [0, 32768)
    }
}

// ---------------------------------------------------------------------------
// Kernel 2: means blocks (partials guaranteed complete by kernel boundary,
// no sync needed) + second half of the broadcast. Means hides under the copy.
// ---------------------------------------------------------------------------
__global__ __launch_bounds__(256) void fused_b_kernel(
    const float* __restrict__ x, float4* __restrict__ out4,
    float* __restrict__ out_means)
{
    int bid = blockIdx.x;
    int tid = threadIdx.x;

    if (bid < MEANS_BLOCKS) {
        // ---- means path: one warp per (k,c) output ----
        int warp_g = (bid * 256 + tid) >> 5;   // 0..4095
        int lane   = tid & 31;
        int k      = warp_g >> 6;

        const float4* prow = (const float4*)&g_partial[warp_g][0];  // 64 f4
        const float4* crow = (const float4*)&g_pcnt[k][0];          // 64 f4

        float4 a  = __ldg(prow + lane);
        float4 b  = __ldg(prow + 32 + lane);
        float4 ca = __ldg(crow + lane);
        float4 cb = __ldg(crow + 32 + lane);

        float s   = (a.x + a.y) + (a.z + a.w) + (b.x + b.y) + (b.z + b.w);
        float cnt = (ca.x + ca.y) + (ca.z + ca.w) + (cb.x + cb.y) + (cb.z + cb.w);

        #pragma unroll
        for (int off = 16; off > 0; off >>= 1) {
            s   += __shfl_xor_sync(0xFFFFFFFFu, s, off);
            cnt += __shfl_xor_sync(0xFFFFFFFFu, cnt, off);
        }

        if (lane == 0) {
            float denom = cnt + (cnt == 0.0f ? 1.0f : 0.0f);
            out_means[warp_g] = s / denom;
        }
    } else {
        // chunks [32768, 65536)
        copy_chunk(x, out4, HALF_CHUNKS + (bid - MEANS_BLOCKS), tid);
    }
}

// ---------------------------------------------------------------------------
extern "C" void kernel_launch(void* const* d_in, const int* in_sizes, int n_in,
                              void* d_out, int out_size)
{
    const float* x  = (const float*)d_in[0];   // [1, 64, 256, 256]
    const float* oh = (const float*)d_in[1];   // [1, 64, 256, 256] one-hot
    float* out = (float*)d_out;

    // Output layout: input_r (K*C*H*W floats) then regional_means (K*C).
    float* out_means = out + (size_t)out_size - (size_t)(K_DIM * C_DIM);

    fused_a_kernel<<<RED_BLOCKS + HALF_CHUNKS, 256>>>(x, oh, (float4*)out);
    fused_b_kernel<<<MEANS_BLOCKS + HALF_CHUNKS, 256>>>(
        x, (float4*)out, out_means);
}